// round 11
// baseline (speedup 1.0000x reference)
#include <cuda_runtime.h>
#include <math.h>

#define NG  3200   // graphs = B*L
#define E   50     // nodes per graph
#define D   100    // embedding dim
#define H   100    // head dim

// Scratch (no allocation allowed in kernel_launch)
__device__ __align__(16) float g_A[D * D];       // A: u[d] = sum_e x0[e]*g_A[e*D+d]
__device__ __align__(16) float g_cp[128];        // Wk @ bq, zero-padded to 128
__device__ __align__(16) float g_bp[128];        // bv + bs, zero-padded to 128
__device__ __align__(16) float g_U[NG * D];      // per-graph u
__device__ __align__(16) float g_wx[NG * 2 * D]; // per-graph packed [w(100) | x0(100)]

// ---------------------------------------------------------------------------
// K1: A = Wk Wq^T (row e per block), block 0 also c = Wk bq and bvs = bv+bs.
// grid = 100 x 128.  Wk staged in smem coalesced (pad-101).
// ---------------------------------------------------------------------------
__global__ void k_pre(const float* __restrict__ Wq, const float* __restrict__ bq,
                      const float* __restrict__ Wk,
                      const float* __restrict__ bv, const float* __restrict__ bs) {
    int b = blockIdx.x, t = threadIdx.x;
    __shared__ float wk[D * 101];   // 40.4KB, pad-101 -> conflict-free rows
    __shared__ float wq[H];
    __shared__ float bqs[H];
    if (t < H) wq[t] = Wq[b * H + t];
    if (b == 0 && t < H) bqs[t] = bq[t];
    for (int i = t; i < D * H; i += 128) {
        int r = i / H, cc = i - r * H;
        wk[r * 101 + cc] = Wk[i];
    }
    __syncthreads();
    if (t < D) {
        float acc = 0.f;
        #pragma unroll 4
        for (int h = 0; h < H; ++h) acc = fmaf(wk[t * 101 + h], wq[h], acc);
        g_A[b * D + t] = acc;
    }
    if (b == 0) {
        float c = 0.f, bb = 0.f;
        if (t < D) {
            #pragma unroll 4
            for (int h = 0; h < H; ++h) c = fmaf(wk[t * 101 + h], bqs[h], c);
            bb = bv[t] + bs[t];
        }
        g_cp[t] = c;   // t in [100,128): zero pad
        g_bp[t] = bb;
    }
}

// ---------------------------------------------------------------------------
// K2: U[g] = c + A x0[g].  CTA = 32 graphs x 32 cols, 256 thr, grid 400.
// Split-K x2 (k-halves of 50) + 2-stage pipelined inner loop; stride-9
// smem reduction merges halves.
// ---------------------------------------------------------------------------
__global__ __launch_bounds__(256) void k_u(const int* __restrict__ nid,
                                           const float* __restrict__ emb) {
    __shared__ float sm[101 * 32 + 32 * D + 128 * 9];
    float* As  = sm;                     // [101][32] (row 100 = zero pad)
    float* xs  = sm + 101 * 32;          // [32][100]
    float* red = xs + 32 * D;            // [128][9]
    __shared__ int ids[32];

    int tid = threadIdx.x;
    int bt = blockIdx.x, gt = bt >> 2, ct = bt & 3;
    int gbase = gt * 32, cbase = ct * 32;

    for (int i = tid; i < 101 * 32; i += 256) {
        int k = i >> 5, col = cbase + (i & 31);
        As[i] = (k < D && col < D) ? g_A[k * D + col] : 0.f;
    }
    if (tid < 32) ids[tid] = nid[(gbase + tid) * E];
    __syncthreads();
    for (int q = tid; q < 32 * (D / 4); q += 256) {      // 800 float4
        int r = q / 25, c = q % 25;
        reinterpret_cast<float4*>(&xs[r * D])[c] =
            reinterpret_cast<const float4*>(emb)[ids[r] * (D / 4) + c];
    }
    __syncthreads();

    int kh = tid >> 7, t = tid & 127;
    int hq = t & 7, h0 = hq * 4;
    int g0 = (t >> 3) * 2;
    int hglob = cbase + h0;
    const float* x0r = &xs[g0 * D + kh * 50];
    const float* x1r = x0r + D;
    const float* wp  = &As[kh * 50 * 32 + h0];

    float4 a0 = make_float4(0.f, 0.f, 0.f, 0.f);
    if (kh == 0) a0 = *reinterpret_cast<const float4*>(&g_cp[hglob]);
    float4 a1 = a0;

    float4 w = *reinterpret_cast<const float4*>(wp);
    float xa = x0r[0], xb = x1r[0];
    #pragma unroll 5
    for (int k = 0; k < 50; ++k) {
        float4 wn = *reinterpret_cast<const float4*>(&wp[(k + 1) * 32]);
        float xan = x0r[k + 1], xbn = x1r[k + 1];    // last prefetch discarded
        a0.x = fmaf(xa, w.x, a0.x); a0.y = fmaf(xa, w.y, a0.y);
        a0.z = fmaf(xa, w.z, a0.z); a0.w = fmaf(xa, w.w, a0.w);
        a1.x = fmaf(xb, w.x, a1.x); a1.y = fmaf(xb, w.y, a1.y);
        a1.z = fmaf(xb, w.z, a1.z); a1.w = fmaf(xb, w.w, a1.w);
        w = wn; xa = xan; xb = xbn;
    }

    if (kh == 1) {
        float* r = &red[t * 9];
        r[0] = a0.x; r[1] = a0.y; r[2] = a0.z; r[3] = a0.w;
        r[4] = a1.x; r[5] = a1.y; r[6] = a1.z; r[7] = a1.w;
    }
    __syncthreads();
    if (kh == 0 && hglob < H) {
        const float* r = &red[t * 9];
        a0.x += r[0]; a0.y += r[1]; a0.z += r[2]; a0.w += r[3];
        a1.x += r[4]; a1.y += r[5]; a1.z += r[6]; a1.w += r[7];
        *reinterpret_cast<float4*>(&g_U[(gbase + g0) * D + hglob]) = a0;
        *reinterpret_cast<float4*>(&g_U[(gbase + g0 + 1) * D + hglob]) = a1;
    }
}

// ---------------------------------------------------------------------------
// K3: per-graph attention, parallel ballot compaction. 1 CTA/graph, 128 thr.
// ---------------------------------------------------------------------------
__global__ __launch_bounds__(128) void k_attn(const int* __restrict__ nid,
                                              const int* __restrict__ adj,
                                              const float* __restrict__ emb) {
    constexpr int LD = 101;
    __shared__ float X[E * LD];
    __shared__ float u_s[D];
    __shared__ float sc[E];
    __shared__ float ps[E];
    __shared__ int ids[E];
    __shared__ unsigned bal[2];
    __shared__ int cnt_s;

    int g = blockIdx.x, tid = threadIdx.x;
    int warp = tid >> 5, lane = tid & 31;

    int myid = 0, m = 0;
    if (tid < E) {
        myid = nid[g * E + tid];
        m    = adj[g * (E * E) + tid * E];   // edge j -> node 0
    }
    if (tid < D) u_s[tid] = g_U[g * D + tid];

    unsigned bw = __ballot_sync(0xffffffffu, m != 0);
    if (warp < 2 && lane == 0) bal[warp] = bw;
    __syncthreads();
    unsigned b0 = bal[0], b1 = bal[1];
    int cnt = __popc(b0) + __popc(b1);
    if (tid == 0) cnt_s = cnt;
    if (tid < E && m) {
        int pos = __popc((warp ? b0 : 0u)) +
                  __popc((warp ? b1 : b0) & ((1u << lane) - 1u));
        ids[pos] = myid;
    }
    __syncthreads();
    cnt = cnt_s;

    for (int q = tid; q < cnt * (D / 4); q += 128) {
        int r = q / 25, cc = q % 25;
        float4 v = reinterpret_cast<const float4*>(emb)[ids[r] * (D / 4) + cc];
        float* dst = &X[r * LD + cc * 4];
        dst[0] = v.x; dst[1] = v.y; dst[2] = v.z; dst[3] = v.w;
    }
    __syncthreads();

    if (tid < cnt) {
        const float* xr = &X[tid * LD];
        float s0 = 0.f, s1 = 0.f;
        #pragma unroll 10
        for (int d2 = 0; d2 < D; d2 += 2) {
            s0 = fmaf(xr[d2],     u_s[d2],     s0);
            s1 = fmaf(xr[d2 + 1], u_s[d2 + 1], s1);
        }
        sc[tid] = (s0 + s1) * 0.1f;          // /sqrt(H)
    }
    __syncthreads();

    float mx = -1e30f;
    for (int j = 0; j < cnt; ++j) mx = fmaxf(mx, sc[j]);
    if (tid < cnt) ps[tid] = __expf(sc[tid] - mx);
    __syncthreads();

    float S = 0.f;
    for (int j = 0; j < cnt; ++j) S += ps[j];
    float inv = 1.0f / S;

    if (tid < D) {
        float w = 0.f;
        for (int j = 0; j < cnt; ++j) w = fmaf(ps[j], X[j * LD + tid], w);
        g_wx[g * (2 * D) + tid]     = w * inv;
        g_wx[g * (2 * D) + D + tid] = X[tid];   // compact row 0 = x0
    }
}

// ---------------------------------------------------------------------------
// K4: out[g] = bvs + [w|x0] @ [Wv;Ws].  CTA = 32 g x 32 c, 256 thr, grid 400.
// Split-K x2 (k-halves of 100) + 2-stage pipelined inner loop + stride-9
// smem reduction.  Wc slice staged straight from Wv/Ws (float4), 1 pad row.
// ---------------------------------------------------------------------------
__global__ __launch_bounds__(256) void k_out(const float* __restrict__ Wv,
                                             const float* __restrict__ Ws,
                                             float* __restrict__ out) {
    extern __shared__ float smo[];
    float* Wcs = smo;                    // [201][32] (row 200 = zero pad)
    float* xs  = smo + 201 * 32;         // [32][200]
    float* red = xs + 32 * 2 * D;        // [128][9]

    int tid = threadIdx.x;
    int bt = blockIdx.x, gt = bt >> 2, ct = bt & 3;
    int gbase = gt * 32, cbase = ct * 32;

    for (int i4 = tid; i4 < 201 * 8; i4 += 256) {        // 1608 float4
        int k = i4 >> 3, col = cbase + (i4 & 7) * 4;
        float4 v = make_float4(0.f, 0.f, 0.f, 0.f);
        if (k < 2 * D && col < H) {
            const float* src = (k < D) ? &Wv[k * H + col] : &Ws[(k - D) * H + col];
            v = *reinterpret_cast<const float4*>(src);
        }
        *reinterpret_cast<float4*>(&Wcs[k * 32 + (i4 & 7) * 4]) = v;
    }
    for (int q = tid; q < 32 * (2 * D / 4); q += 256)    // 1600 float4, coalesced
        reinterpret_cast<float4*>(xs)[q] =
            reinterpret_cast<const float4*>(g_wx)[gbase * (2 * D / 4) + q];
    __syncthreads();

    int kh = tid >> 7, t = tid & 127;
    int hq = t & 7, h0 = hq * 4;
    int g0 = (t >> 3) * 2;
    int hglob = cbase + h0;
    const float* x0r = &xs[g0 * 2 * D + kh * D];
    const float* x1r = x0r + 2 * D;
    const float* wp  = &Wcs[kh * D * 32 + h0];

    float4 a0 = make_float4(0.f, 0.f, 0.f, 0.f);
    if (kh == 0) a0 = *reinterpret_cast<const float4*>(&g_bp[hglob]);
    float4 a1 = a0;

    float4 w = *reinterpret_cast<const float4*>(wp);
    float xa = x0r[0], xb = x1r[0];
    #pragma unroll 5
    for (int k = 0; k < D; ++k) {
        float4 wn = *reinterpret_cast<const float4*>(&wp[(k + 1) * 32]);
        float xan = x0r[k + 1], xbn = x1r[k + 1];    // last prefetch discarded
        a0.x = fmaf(xa, w.x, a0.x); a0.y = fmaf(xa, w.y, a0.y);
        a0.z = fmaf(xa, w.z, a0.z); a0.w = fmaf(xa, w.w, a0.w);
        a1.x = fmaf(xb, w.x, a1.x); a1.y = fmaf(xb, w.y, a1.y);
        a1.z = fmaf(xb, w.z, a1.z); a1.w = fmaf(xb, w.w, a1.w);
        w = wn; xa = xan; xb = xbn;
    }

    if (kh == 1) {
        float* r = &red[t * 9];
        r[0] = a0.x; r[1] = a0.y; r[2] = a0.z; r[3] = a0.w;
        r[4] = a1.x; r[5] = a1.y; r[6] = a1.z; r[7] = a1.w;
    }
    __syncthreads();
    if (kh == 0 && hglob < H) {
        const float* r = &red[t * 9];
        a0.x += r[0]; a0.y += r[1]; a0.z += r[2]; a0.w += r[3];
        a1.x += r[4]; a1.y += r[5]; a1.z += r[6]; a1.w += r[7];
        *reinterpret_cast<float4*>(&out[(gbase + g0) * H + hglob]) = a0;
        *reinterpret_cast<float4*>(&out[(gbase + g0 + 1) * H + hglob]) = a1;
    }
}

// ---------------------------------------------------------------------------
extern "C" void kernel_launch(void* const* d_in, const int* in_sizes, int n_in,
                              void* d_out, int out_size) {
    const int*   nid = (const int*)d_in[0];
    const int*   adj = (const int*)d_in[1];
    const float* emb = (const float*)d_in[2];
    const float* Wq  = (const float*)d_in[3];
    const float* bq  = (const float*)d_in[4];
    const float* Wk  = (const float*)d_in[5];
    // d_in[6] = bk: cancels in softmax (constant per-row shift)
    const float* Wv  = (const float*)d_in[7];
    const float* bv  = (const float*)d_in[8];
    const float* Ws  = (const float*)d_in[9];
    const float* bs  = (const float*)d_in[10];
    float* out = (float*)d_out;

    const int smemO = (201 * 32 + 32 * 2 * D + 128 * 9) * (int)sizeof(float); // ~56KB
    cudaFuncSetAttribute(k_out, cudaFuncAttributeMaxDynamicSharedMemorySize, smemO);

    k_pre<<<D, 128>>>(Wq, bq, Wk, bv, bs);
    k_u<<<400, 256>>>(nid, emb);
    k_attn<<<NG, 128>>>(nid, adj, emb);
    k_out<<<400, 256, smemO>>>(Wv, Ws, out);
}